// round 4
// baseline (speedup 1.0000x reference)
#include <cuda_runtime.h>
#include <cuda_bf16.h>
#include <cstdint>

#define B   32
#define N   2048
#define VD  256
#define LR  64
#define EMB 256
#define ROWS (B*N)
#define EPS_DIAG 1e-6f
#define EPS_BN   1e-5f

// Scratch (device globals)
__device__ float g_W[128 * 256];      // interleaved: row c even -> W1[c/2], odd -> W2[c/2]
__device__ float g_bias[128];
__device__ float g_right[(size_t)ROWS * LR];   // 16 MB
__device__ float g_dr[ROWS];
__device__ float g_s[B * LR];
__device__ float g_vfinal[B * VD];

__device__ __forceinline__ uint32_t to_tf32(float x) {
    uint32_t y;
    asm("cvt.rna.tf32.f32 %0, %1;" : "=r"(y) : "f"(x));
    return y;
}

__device__ __forceinline__ void mma_tf32(float c[4], const uint32_t a[4], const uint32_t b[2]) {
    asm volatile(
        "mma.sync.aligned.m16n8k8.row.col.f32.tf32.tf32.f32 "
        "{%0,%1,%2,%3}, {%4,%5,%6,%7}, {%8,%9}, {%0,%1,%2,%3};"
        : "+f"(c[0]), "+f"(c[1]), "+f"(c[2]), "+f"(c[3])
        : "r"(a[0]), "r"(a[1]), "r"(a[2]), "r"(a[3]), "r"(b[0]), "r"(b[1]));
}

__device__ __forceinline__ void cp_async16(uint32_t dst_smem, const void* src) {
    asm volatile("cp.async.ca.shared.global [%0], [%1], 16;" :: "r"(dst_smem), "l"(src));
}

// ---------------------------------------------------------------------------
// Kernel A: weight norm + zero accumulators.  grid 128, block 256
__global__ void k_weightnorm(const float* __restrict__ U1_v, const float* __restrict__ U1_g,
                             const float* __restrict__ U1_b, const float* __restrict__ U2_v,
                             const float* __restrict__ U2_g, const float* __restrict__ U2_b)
{
    int row = blockIdx.x;
    int l = row >> 1;
    bool odd = row & 1;
    const float* v = (odd ? U2_v : U1_v) + l * VD;
    const float* g = odd ? U2_g : U1_g;
    const float* bb = odd ? U2_b : U1_b;
    int tid = threadIdx.x;

    float x = v[tid];
    float ss = x * x;
    #pragma unroll
    for (int off = 16; off >= 1; off >>= 1) ss += __shfl_xor_sync(0xffffffff, ss, off);
    __shared__ float warp_ss[8];
    __shared__ float scale_sh;
    if ((tid & 31) == 0) warp_ss[tid >> 5] = ss;
    __syncthreads();
    if (tid == 0) {
        float tot = 0.f;
        #pragma unroll
        for (int w = 0; w < 8; w++) tot += warp_ss[w];
        scale_sh = g[l] * rsqrtf(tot);
    }
    __syncthreads();
    g_W[row * 256 + tid] = x * scale_sh;
    if (tid == 0) g_bias[row] = bb[l];

    int idx = blockIdx.x * 256 + tid;
    if (idx < B * LR) g_s[idx] = 0.f;
    if (idx < B * VD) g_vfinal[idx] = 0.f;
}

// ---------------------------------------------------------------------------
// Kernel C: tf32 tensor-core GEMM [65536x256] @ W^T[256x128] + fused epilogue.
// cp.async double-buffered pipeline, K-chunk 16, 2 stages.
// grid 512 (row tiles of 128), block 256 (8 warps: 4 m x 2 n).
__global__ void __launch_bounds__(256, 2) k_main(const float* __restrict__ Vmat)
{
    __shared__ float As[2][128][20];   // [stage][row][k], pad 20 (80B rows, 16B-aligned)
    __shared__ float Bs[2][128][20];   // [stage][col][k]
    __shared__ float d_sh[128];
    __shared__ float s_sh[64];
    __shared__ float bias_sh[128];

    int tid = threadIdx.x;
    int lane = tid & 31, wid = tid >> 5;
    int warp_m = wid & 3, warp_n = wid >> 2;     // warp tile: 32 rows x 64 cols
    int qr = lane >> 2, qk = lane & 3;
    int tileRow0 = blockIdx.x * 128;
    int batch = blockIdx.x >> 4;                 // 16 tiles per batch

    if (tid < 128) { d_sh[tid] = 0.f; bias_sh[tid] = g_bias[tid]; }
    if (tid < 64) s_sh[tid] = 0.f;

    float acc[2][8][4];
    #pragma unroll
    for (int mt = 0; mt < 2; mt++)
        #pragma unroll
        for (int nt = 0; nt < 8; nt++)
            #pragma unroll
            for (int c = 0; c < 4; c++) acc[mt][nt][c] = 0.f;

    const float* Vbase = Vmat + (size_t)tileRow0 * VD;
    uint32_t sA = (uint32_t)__cvta_generic_to_shared(&As[0][0][0]);
    uint32_t sB = (uint32_t)__cvta_generic_to_shared(&Bs[0][0][0]);

    // chunk issue: 128 rows x 16 floats = 512 x 16B segs per array; 2 per thread
    int seg0 = tid, seg1 = tid + 256;
    int r0 = seg0 >> 2, p0 = seg0 & 3;
    int r1 = seg1 >> 2, p1 = seg1 & 3;

    #define ISSUE_CHUNK(kc, st) do {                                              \
        int k0_ = (kc) * 16;                                                      \
        cp_async16(sA + ((st) * 128 + r0) * 80 + p0 * 16,                         \
                   Vbase + (size_t)r0 * VD + k0_ + p0 * 4);                       \
        cp_async16(sA + ((st) * 128 + r1) * 80 + p1 * 16,                         \
                   Vbase + (size_t)r1 * VD + k0_ + p1 * 4);                       \
        cp_async16(sB + ((st) * 128 + r0) * 80 + p0 * 16,                         \
                   g_W + r0 * 256 + k0_ + p0 * 4);                                \
        cp_async16(sB + ((st) * 128 + r1) * 80 + p1 * 16,                         \
                   g_W + r1 * 256 + k0_ + p1 * 4);                                \
        asm volatile("cp.async.commit_group;");                                   \
    } while (0)

    ISSUE_CHUNK(0, 0);

    for (int kc = 0; kc < 16; kc++) {
        int st = kc & 1;
        if (kc < 15) {
            ISSUE_CHUNK(kc + 1, (kc + 1) & 1);
            asm volatile("cp.async.wait_group 1;");
        } else {
            asm volatile("cp.async.wait_group 0;");
        }
        __syncthreads();

        #pragma unroll
        for (int ks = 0; ks < 2; ks++) {
            int kb = ks * 8 + qk;
            uint32_t af[2][4];
            #pragma unroll
            for (int mt = 0; mt < 2; mt++) {
                int r = warp_m * 32 + mt * 16 + qr;
                af[mt][0] = to_tf32(As[st][r][kb]);
                af[mt][1] = to_tf32(As[st][r + 8][kb]);
                af[mt][2] = to_tf32(As[st][r][kb + 4]);
                af[mt][3] = to_tf32(As[st][r + 8][kb + 4]);
            }
            uint32_t bf[8][2];
            #pragma unroll
            for (int nt = 0; nt < 8; nt++) {
                int c = warp_n * 64 + nt * 8 + qr;
                bf[nt][0] = to_tf32(Bs[st][c][kb]);
                bf[nt][1] = to_tf32(Bs[st][c][kb + 4]);
            }
            #pragma unroll
            for (int mt = 0; mt < 2; mt++)
                #pragma unroll
                for (int nt = 0; nt < 8; nt++)
                    mma_tf32(acc[mt][nt], af[mt], bf[nt]);
        }
        __syncthreads();
    }
    #undef ISSUE_CHUNK

    // ---- epilogue: bias+relu, d per row, dr, store right, accumulate s ----
    float be[8], bo[8];
    #pragma unroll
    for (int nt = 0; nt < 8; nt++) {
        int c0 = warp_n * 64 + nt * 8 + qk * 2;
        be[nt] = bias_sh[c0];
        bo[nt] = bias_sh[c0 + 1];
    }

    #pragma unroll
    for (int mt = 0; mt < 2; mt++) {
        #pragma unroll
        for (int h = 0; h < 2; h++) {
            float dpart = 0.f;
            #pragma unroll
            for (int nt = 0; nt < 8; nt++) {
                float rv = fmaxf(acc[mt][nt][h * 2]     + be[nt], 0.f);
                float lv = fmaxf(acc[mt][nt][h * 2 + 1] + bo[nt], 0.f);
                acc[mt][nt][h * 2] = rv;
                acc[mt][nt][h * 2 + 1] = lv;
                dpart = fmaf(rv, lv, dpart);
            }
            dpart += __shfl_xor_sync(0xffffffff, dpart, 1);
            dpart += __shfl_xor_sync(0xffffffff, dpart, 2);
            if (qk == 0) {
                int rl = warp_m * 32 + mt * 16 + h * 8 + qr;
                atomicAdd(&d_sh[rl], dpart);
            }
        }
    }
    __syncthreads();

    float s_t[8];
    #pragma unroll
    for (int nt = 0; nt < 8; nt++) s_t[nt] = 0.f;

    #pragma unroll
    for (int mt = 0; mt < 2; mt++) {
        #pragma unroll
        for (int h = 0; h < 2; h++) {
            int rl = warp_m * 32 + mt * 16 + h * 8 + qr;
            float dr = rsqrtf(d_sh[rl] + EPS_DIAG);
            int row = tileRow0 + rl;
            if (warp_n == 0 && qk == 0) g_dr[row] = dr;
            float* rp = g_right + (size_t)row * LR + warp_n * 32;
            #pragma unroll
            for (int nt = 0; nt < 8; nt++) {
                rp[nt * 4 + qk] = acc[mt][nt][h * 2];
                s_t[nt] = fmaf(dr, acc[mt][nt][h * 2 + 1], s_t[nt]);
            }
        }
    }
    #pragma unroll
    for (int off = 4; off <= 16; off <<= 1)
        #pragma unroll
        for (int nt = 0; nt < 8; nt++)
            s_t[nt] += __shfl_xor_sync(0xffffffff, s_t[nt], off);
    if (qr == 0) {
        #pragma unroll
        for (int nt = 0; nt < 8; nt++)
            atomicAdd(&s_sh[warp_n * 32 + nt * 4 + qk], s_t[nt]);
    }
    __syncthreads();
    if (tid < 64) atomicAdd(&g_s[batch * LR + tid], s_sh[tid]);
}

// ---------------------------------------------------------------------------
// Kernel D: c[m] = N+1 - dr[m]*(s . right[m]); v_final += (1/N)*c[m]*Vmat[m,:]
// grid (4, 32), block 256. Block covers 512 rows of one batch.
// Phase 2: 4 m-groups x 64 threads x float4 columns -> high MLP.
__global__ void __launch_bounds__(256) k_final(const float* __restrict__ Vmat)
{
    __shared__ float s_sh[64];
    __shared__ float c_sh[512];
    __shared__ float red[4][256];
    int tid = threadIdx.x;
    int b = blockIdx.y;
    int m0 = blockIdx.x * 512;

    if (tid < 64) s_sh[tid] = g_s[b * LR + tid];
    __syncthreads();

    #pragma unroll
    for (int i = 0; i < 2; i++) {
        int row = b * N + m0 + tid + i * 256;
        const float4* rp = (const float4*)(g_right + (size_t)row * LR);
        float dot = 0.f;
        #pragma unroll
        for (int q = 0; q < 16; q++) {
            float4 v = rp[q];
            dot = fmaf(v.x, s_sh[q * 4 + 0], dot);
            dot = fmaf(v.y, s_sh[q * 4 + 1], dot);
            dot = fmaf(v.z, s_sh[q * 4 + 2], dot);
            dot = fmaf(v.w, s_sh[q * 4 + 3], dot);
        }
        c_sh[tid + i * 256] = (float)(N + 1) - g_dr[row] * dot;
    }
    __syncthreads();

    int g = tid >> 6;            // m-group 0..3 (128 rows each)
    int c4 = (tid & 63) * 4;     // column base
    const float* Vp = Vmat + ((size_t)(b * N + m0 + g * 128)) * VD + c4;
    const float* cp = &c_sh[g * 128];
    float4 vac = make_float4(0.f, 0.f, 0.f, 0.f);
    #pragma unroll 8
    for (int j = 0; j < 128; j++) {
        float4 v = *(const float4*)(Vp + (size_t)j * VD);
        float cc = cp[j];
        vac.x = fmaf(cc, v.x, vac.x);
        vac.y = fmaf(cc, v.y, vac.y);
        vac.z = fmaf(cc, v.z, vac.z);
        vac.w = fmaf(cc, v.w, vac.w);
    }
    *(float4*)&red[g][c4] = vac;
    __syncthreads();

    // tid -> column; sum 4 groups; one atomic per column per block
    float sum = red[0][tid] + red[1][tid] + red[2][tid] + red[3][tid];
    atomicAdd(&g_vfinal[b * VD + tid], sum * (1.0f / (float)N));
}

// ---------------------------------------------------------------------------
// Kernel E: feat = v_final @ W_lin^T + b_lin; BatchNorm over B (biased var).
// grid 256 (one embed col per block), block 256 (warp w -> 4 batches).
__global__ void __launch_bounds__(256) k_bn(const float* __restrict__ W_lin,
                                            const float* __restrict__ b_lin,
                                            const float* __restrict__ gamma,
                                            const float* __restrict__ beta,
                                            float* __restrict__ out)
{
    int e = blockIdx.x;
    int tid = threadIdx.x;
    int w = tid >> 5, lane = tid & 31;
    int bat = w * 4 + (lane >> 3);   // 0..31
    int dl = lane & 7;

    const float* wrow = W_lin + e * VD;
    const float* vrow = g_vfinal + bat * VD;
    float part = 0.f;
    #pragma unroll
    for (int j = 0; j < 32; j++) {
        int d = dl + 8 * j;
        part = fmaf(vrow[d], wrow[d], part);
    }
    part += __shfl_xor_sync(0xffffffff, part, 1);
    part += __shfl_xor_sync(0xffffffff, part, 2);
    part += __shfl_xor_sync(0xffffffff, part, 4);

    __shared__ float feats[32];
    if (dl == 0) feats[bat] = part + b_lin[e];
    __syncthreads();

    if (tid < 32) {
        float f = feats[tid];
        float mu = f;
        #pragma unroll
        for (int off = 16; off >= 1; off >>= 1) mu += __shfl_xor_sync(0xffffffff, mu, off);
        mu *= (1.0f / 32.0f);
        float df = f - mu;
        float vv = df * df;
        #pragma unroll
        for (int off = 16; off >= 1; off >>= 1) vv += __shfl_xor_sync(0xffffffff, vv, off);
        vv *= (1.0f / 32.0f);
        out[tid * EMB + e] = df * rsqrtf(vv + EPS_BN) * gamma[e] + beta[e];
    }
}

// ---------------------------------------------------------------------------
extern "C" void kernel_launch(void* const* d_in, const int* in_sizes, int n_in,
                              void* d_out, int out_size)
{
    const float* Vmat  = (const float*)d_in[0];
    const float* U1_v  = (const float*)d_in[1];
    const float* U1_g  = (const float*)d_in[2];
    const float* U1_b  = (const float*)d_in[3];
    const float* U2_v  = (const float*)d_in[4];
    const float* U2_g  = (const float*)d_in[5];
    const float* U2_b  = (const float*)d_in[6];
    const float* W_lin = (const float*)d_in[7];
    const float* b_lin = (const float*)d_in[8];
    const float* gamma = (const float*)d_in[9];
    const float* beta  = (const float*)d_in[10];
    float* out = (float*)d_out;

    k_weightnorm<<<128, 256>>>(U1_v, U1_g, U1_b, U2_v, U2_g, U2_b);
    k_main<<<ROWS / 128, 256>>>(Vmat);
    k_final<<<dim3(4, B), 256>>>(Vmat);
    k_bn<<<EMB, 256>>>(W_lin, b_lin, gamma, beta, out);
}

// round 5
// speedup vs baseline: 1.0949x; 1.0949x over previous
#include <cuda_runtime.h>
#include <cuda_bf16.h>
#include <cstdint>

#define B   32
#define N   2048
#define VD  256
#define LR  64
#define EMB 256
#define ROWS (B*N)
#define EPS_DIAG 1e-6f
#define EPS_BN   1e-5f

// Scratch (device globals)
__device__ float g_W[128 * 256];      // interleaved: row c even -> W1[c/2], odd -> W2[c/2]
__device__ float g_bias[128];
__device__ float g_right[(size_t)ROWS * LR];   // 16 MB
__device__ float g_dr[ROWS];
__device__ float g_s[B * LR];
__device__ float g_vfinal[B * VD];

__device__ __forceinline__ uint32_t to_tf32(float x) {
    uint32_t y;
    asm("cvt.rna.tf32.f32 %0, %1;" : "=r"(y) : "f"(x));
    return y;
}

__device__ __forceinline__ void mma_tf32(float c[4], const uint32_t a[4], const uint32_t b[2]) {
    asm volatile(
        "mma.sync.aligned.m16n8k8.row.col.f32.tf32.tf32.f32 "
        "{%0,%1,%2,%3}, {%4,%5,%6,%7}, {%8,%9}, {%0,%1,%2,%3};"
        : "+f"(c[0]), "+f"(c[1]), "+f"(c[2]), "+f"(c[3])
        : "r"(a[0]), "r"(a[1]), "r"(a[2]), "r"(a[3]), "r"(b[0]), "r"(b[1]));
}

// ---------------------------------------------------------------------------
// Kernel A: weight norm + zero accumulators.  grid 128, block 256
__global__ void k_weightnorm(const float* __restrict__ U1_v, const float* __restrict__ U1_g,
                             const float* __restrict__ U1_b, const float* __restrict__ U2_v,
                             const float* __restrict__ U2_g, const float* __restrict__ U2_b)
{
    int row = blockIdx.x;
    int l = row >> 1;
    bool odd = row & 1;
    const float* v = (odd ? U2_v : U1_v) + l * VD;
    const float* g = odd ? U2_g : U1_g;
    const float* bb = odd ? U2_b : U1_b;
    int tid = threadIdx.x;

    float x = v[tid];
    float ss = x * x;
    #pragma unroll
    for (int off = 16; off >= 1; off >>= 1) ss += __shfl_xor_sync(0xffffffff, ss, off);
    __shared__ float warp_ss[8];
    __shared__ float scale_sh;
    if ((tid & 31) == 0) warp_ss[tid >> 5] = ss;
    __syncthreads();
    if (tid == 0) {
        float tot = 0.f;
        #pragma unroll
        for (int w = 0; w < 8; w++) tot += warp_ss[w];
        scale_sh = g[l] * rsqrtf(tot);
    }
    __syncthreads();
    g_W[row * 256 + tid] = x * scale_sh;
    if (tid == 0) g_bias[row] = bb[l];

    int idx = blockIdx.x * 256 + tid;
    if (idx < B * LR) g_s[idx] = 0.f;
    if (idx < B * VD) g_vfinal[idx] = 0.f;
}

// ---------------------------------------------------------------------------
// Kernel C: tf32 tensor-core GEMM [65536x256] @ W^T[256x128] + fused epilogue.
// (R3-measured version: register prefetch, K-chunk 32, cvt at smem store.)
// grid 512 (row tiles of 128), block 256 (8 warps: 4 m x 2 n).
__global__ void __launch_bounds__(256, 2) k_main(const float* __restrict__ Vmat)
{
    __shared__ uint32_t As[128][36];   // [row][k-in-chunk] (tf32 bits), pad 36
    __shared__ uint32_t Bs[128][36];   // [col][k-in-chunk]
    __shared__ float d_sh[128];
    __shared__ float s_sh[64];
    __shared__ float bias_sh[128];

    int tid = threadIdx.x;
    int lane = tid & 31, wid = tid >> 5;
    int warp_m = wid & 3, warp_n = wid >> 2;     // warp tile: 32 rows x 64 cols
    int qr = lane >> 2, qk = lane & 3;
    int tileRow0 = blockIdx.x * 128;
    int batch = blockIdx.x >> 4;                 // 16 tiles per batch

    if (tid < 128) { d_sh[tid] = 0.f; bias_sh[tid] = g_bias[tid]; }
    if (tid < 64) s_sh[tid] = 0.f;

    float acc[2][8][4];
    #pragma unroll
    for (int mt = 0; mt < 2; mt++)
        #pragma unroll
        for (int nt = 0; nt < 8; nt++)
            #pragma unroll
            for (int c = 0; c < 4; c++) acc[mt][nt][c] = 0.f;

    const float* Vbase = Vmat + (size_t)tileRow0 * VD;
    int lrow = tid >> 3;      // base row within the 32-row load slab
    int lkq  = tid & 7;       // float4 index within 32-k chunk

    float4 ra[4], rb[4];
    // prefetch chunk 0
    #pragma unroll
    for (int i = 0; i < 4; i++) {
        int r = i * 32 + lrow;
        ra[i] = *(const float4*)(Vbase + (size_t)r * VD + lkq * 4);
        rb[i] = *(const float4*)(g_W + r * 256 + lkq * 4);
    }

    for (int kc = 0; kc < 8; kc++) {
        __syncthreads();
        #pragma unroll
        for (int i = 0; i < 4; i++) {
            int r = i * 32 + lrow;
            uint4 a, b;
            a.x = to_tf32(ra[i].x); a.y = to_tf32(ra[i].y);
            a.z = to_tf32(ra[i].z); a.w = to_tf32(ra[i].w);
            b.x = to_tf32(rb[i].x); b.y = to_tf32(rb[i].y);
            b.z = to_tf32(rb[i].z); b.w = to_tf32(rb[i].w);
            *(uint4*)&As[r][lkq * 4] = a;
            *(uint4*)&Bs[r][lkq * 4] = b;
        }
        __syncthreads();
        if (kc < 7) {
            int k0 = (kc + 1) * 32;
            #pragma unroll
            for (int i = 0; i < 4; i++) {
                int r = i * 32 + lrow;
                ra[i] = *(const float4*)(Vbase + (size_t)r * VD + k0 + lkq * 4);
                rb[i] = *(const float4*)(g_W + r * 256 + k0 + lkq * 4);
            }
        }
        #pragma unroll
        for (int ks = 0; ks < 4; ks++) {
            int kb = ks * 8 + qk;
            uint32_t af[2][4];
            #pragma unroll
            for (int mt = 0; mt < 2; mt++) {
                int r = warp_m * 32 + mt * 16 + qr;
                af[mt][0] = As[r][kb];
                af[mt][1] = As[r + 8][kb];
                af[mt][2] = As[r][kb + 4];
                af[mt][3] = As[r + 8][kb + 4];
            }
            uint32_t bf[8][2];
            #pragma unroll
            for (int nt = 0; nt < 8; nt++) {
                int c = warp_n * 64 + nt * 8 + qr;
                bf[nt][0] = Bs[c][kb];
                bf[nt][1] = Bs[c][kb + 4];
            }
            #pragma unroll
            for (int mt = 0; mt < 2; mt++)
                #pragma unroll
                for (int nt = 0; nt < 8; nt++)
                    mma_tf32(acc[mt][nt], af[mt], bf[nt]);
        }
    }

    // ---- epilogue: bias+relu, d per row, dr, store right, accumulate s ----
    float be[8], bo[8];
    #pragma unroll
    for (int nt = 0; nt < 8; nt++) {
        int c0 = warp_n * 64 + nt * 8 + qk * 2;
        be[nt] = bias_sh[c0];
        bo[nt] = bias_sh[c0 + 1];
    }

    #pragma unroll
    for (int mt = 0; mt < 2; mt++) {
        #pragma unroll
        for (int h = 0; h < 2; h++) {
            float dpart = 0.f;
            #pragma unroll
            for (int nt = 0; nt < 8; nt++) {
                float rv = fmaxf(acc[mt][nt][h * 2]     + be[nt], 0.f);
                float lv = fmaxf(acc[mt][nt][h * 2 + 1] + bo[nt], 0.f);
                acc[mt][nt][h * 2] = rv;
                acc[mt][nt][h * 2 + 1] = lv;
                dpart = fmaf(rv, lv, dpart);
            }
            dpart += __shfl_xor_sync(0xffffffff, dpart, 1);
            dpart += __shfl_xor_sync(0xffffffff, dpart, 2);
            if (qk == 0) {
                int rl = warp_m * 32 + mt * 16 + h * 8 + qr;
                atomicAdd(&d_sh[rl], dpart);
            }
        }
    }
    __syncthreads();

    float s_t[8];
    #pragma unroll
    for (int nt = 0; nt < 8; nt++) s_t[nt] = 0.f;

    #pragma unroll
    for (int mt = 0; mt < 2; mt++) {
        #pragma unroll
        for (int h = 0; h < 2; h++) {
            int rl = warp_m * 32 + mt * 16 + h * 8 + qr;
            float dr = rsqrtf(d_sh[rl] + EPS_DIAG);
            int row = tileRow0 + rl;
            if (warp_n == 0 && qk == 0) g_dr[row] = dr;
            float* rp = g_right + (size_t)row * LR + warp_n * 32;
            #pragma unroll
            for (int nt = 0; nt < 8; nt++) {
                rp[nt * 4 + qk] = acc[mt][nt][h * 2];
                s_t[nt] = fmaf(dr, acc[mt][nt][h * 2 + 1], s_t[nt]);
            }
        }
    }
    #pragma unroll
    for (int off = 4; off <= 16; off <<= 1)
        #pragma unroll
        for (int nt = 0; nt < 8; nt++)
            s_t[nt] += __shfl_xor_sync(0xffffffff, s_t[nt], off);
    if (qr == 0) {
        #pragma unroll
        for (int nt = 0; nt < 8; nt++)
            atomicAdd(&s_sh[warp_n * 32 + nt * 4 + qk], s_t[nt]);
    }
    __syncthreads();
    if (tid < 64) atomicAdd(&g_s[batch * LR + tid], s_sh[tid]);
}

// ---------------------------------------------------------------------------
// Kernel D: c[m] = N+1 - dr[m]*(s . right[m]); v_final += (1/N)*c[m]*Vmat[m,:]
// grid (4, 32), block 256. Block covers 512 rows of one batch.
// Phase 2: 4 m-groups x 64 threads x float4 columns -> high MLP.
__global__ void __launch_bounds__(256) k_final(const float* __restrict__ Vmat)
{
    __shared__ float s_sh[64];
    __shared__ float c_sh[512];
    __shared__ float red[4][256];
    int tid = threadIdx.x;
    int b = blockIdx.y;
    int m0 = blockIdx.x * 512;

    if (tid < 64) s_sh[tid] = g_s[b * LR + tid];
    __syncthreads();

    #pragma unroll
    for (int i = 0; i < 2; i++) {
        int row = b * N + m0 + tid + i * 256;
        const float4* rp = (const float4*)(g_right + (size_t)row * LR);
        float dot = 0.f;
        #pragma unroll
        for (int q = 0; q < 16; q++) {
            float4 v = rp[q];
            dot = fmaf(v.x, s_sh[q * 4 + 0], dot);
            dot = fmaf(v.y, s_sh[q * 4 + 1], dot);
            dot = fmaf(v.z, s_sh[q * 4 + 2], dot);
            dot = fmaf(v.w, s_sh[q * 4 + 3], dot);
        }
        c_sh[tid + i * 256] = (float)(N + 1) - g_dr[row] * dot;
    }
    __syncthreads();

    int g = tid >> 6;            // m-group 0..3 (128 rows each)
    int c4 = (tid & 63) * 4;     // column base
    const float* Vp = Vmat + ((size_t)(b * N + m0 + g * 128)) * VD + c4;
    const float* cp = &c_sh[g * 128];
    float4 vac = make_float4(0.f, 0.f, 0.f, 0.f);
    #pragma unroll 8
    for (int j = 0; j < 128; j++) {
        float4 v = *(const float4*)(Vp + (size_t)j * VD);
        float cc = cp[j];
        vac.x = fmaf(cc, v.x, vac.x);
        vac.y = fmaf(cc, v.y, vac.y);
        vac.z = fmaf(cc, v.z, vac.z);
        vac.w = fmaf(cc, v.w, vac.w);
    }
    *(float4*)&red[g][c4] = vac;
    __syncthreads();

    // tid -> column; sum 4 groups; one atomic per column per block
    float sum = red[0][tid] + red[1][tid] + red[2][tid] + red[3][tid];
    atomicAdd(&g_vfinal[b * VD + tid], sum * (1.0f / (float)N));
}

// ---------------------------------------------------------------------------
// Kernel E: feat = v_final @ W_lin^T + b_lin; BatchNorm over B (biased var).
// grid 256 (one embed col per block), block 256 (warp w -> 4 batches).
__global__ void __launch_bounds__(256) k_bn(const float* __restrict__ W_lin,
                                            const float* __restrict__ b_lin,
                                            const float* __restrict__ gamma,
                                            const float* __restrict__ beta,
                                            float* __restrict__ out)
{
    int e = blockIdx.x;
    int tid = threadIdx.x;
    int w = tid >> 5, lane = tid & 31;
    int bat = w * 4 + (lane >> 3);   // 0..31
    int dl = lane & 7;

    const float* wrow = W_lin + e * VD;
    const float* vrow = g_vfinal + bat * VD;
    float part = 0.f;
    #pragma unroll
    for (int j = 0; j < 32; j++) {
        int d = dl + 8 * j;
        part = fmaf(vrow[d], wrow[d], part);
    }
    part += __shfl_xor_sync(0xffffffff, part, 1);
    part += __shfl_xor_sync(0xffffffff, part, 2);
    part += __shfl_xor_sync(0xffffffff, part, 4);

    __shared__ float feats[32];
    if (dl == 0) feats[bat] = part + b_lin[e];
    __syncthreads();

    if (tid < 32) {
        float f = feats[tid];
        float mu = f;
        #pragma unroll
        for (int off = 16; off >= 1; off >>= 1) mu += __shfl_xor_sync(0xffffffff, mu, off);
        mu *= (1.0f / 32.0f);
        float df = f - mu;
        float vv = df * df;
        #pragma unroll
        for (int off = 16; off >= 1; off >>= 1) vv += __shfl_xor_sync(0xffffffff, vv, off);
        vv *= (1.0f / 32.0f);
        out[tid * EMB + e] = df * rsqrtf(vv + EPS_BN) * gamma[e] + beta[e];
    }
}

// ---------------------------------------------------------------------------
extern "C" void kernel_launch(void* const* d_in, const int* in_sizes, int n_in,
                              void* d_out, int out_size)
{
    const float* Vmat  = (const float*)d_in[0];
    const float* U1_v  = (const float*)d_in[1];
    const float* U1_g  = (const float*)d_in[2];
    const float* U1_b  = (const float*)d_in[3];
    const float* U2_v  = (const float*)d_in[4];
    const float* U2_g  = (const float*)d_in[5];
    const float* U2_b  = (const float*)d_in[6];
    const float* W_lin = (const float*)d_in[7];
    const float* b_lin = (const float*)d_in[8];
    const float* gamma = (const float*)d_in[9];
    const float* beta  = (const float*)d_in[10];
    float* out = (float*)d_out;

    k_weightnorm<<<128, 256>>>(U1_v, U1_g, U1_b, U2_v, U2_g, U2_b);
    k_main<<<ROWS / 128, 256>>>(Vmat);
    k_final<<<dim3(4, B), 256>>>(Vmat);
    k_bn<<<EMB, 256>>>(W_lin, b_lin, gamma, beta, out);
}

// round 6
// speedup vs baseline: 1.3242x; 1.2095x over previous
#include <cuda_runtime.h>
#include <cuda_fp16.h>
#include <cuda_bf16.h>
#include <cstdint>

#define B   32
#define N   2048
#define VD  256
#define LR  64
#define EMB 256
#define ROWS (B*N)
#define EPS_DIAG 1e-6f
#define EPS_BN   1e-5f

// Scratch (device globals)
__device__ float g_W[128 * 256];      // interleaved: row c even -> W1[c/2], odd -> W2[c/2]
__device__ float g_bias[128];
__device__ float g_right[(size_t)ROWS * LR];   // 16 MB
__device__ float g_dr[ROWS];
__device__ float g_s[B * LR];
__device__ float g_vfinal[B * VD];

__device__ __forceinline__ uint32_t pack_h2(float lo, float hi) {
    __half2 h = __floats2half2_rn(lo, hi);
    return *(uint32_t*)&h;
}

__device__ __forceinline__ void mma_f16(float c[4], const uint32_t a[4], const uint32_t b[2]) {
    asm volatile(
        "mma.sync.aligned.m16n8k16.row.col.f32.f16.f16.f32 "
        "{%0,%1,%2,%3}, {%4,%5,%6,%7}, {%8,%9}, {%0,%1,%2,%3};"
        : "+f"(c[0]), "+f"(c[1]), "+f"(c[2]), "+f"(c[3])
        : "r"(a[0]), "r"(a[1]), "r"(a[2]), "r"(a[3]), "r"(b[0]), "r"(b[1]));
}

// ---------------------------------------------------------------------------
// Kernel A: weight norm + zero accumulators.  grid 128, block 256
__global__ void k_weightnorm(const float* __restrict__ U1_v, const float* __restrict__ U1_g,
                             const float* __restrict__ U1_b, const float* __restrict__ U2_v,
                             const float* __restrict__ U2_g, const float* __restrict__ U2_b)
{
    int row = blockIdx.x;
    int l = row >> 1;
    bool odd = row & 1;
    const float* v = (odd ? U2_v : U1_v) + l * VD;
    const float* g = odd ? U2_g : U1_g;
    const float* bb = odd ? U2_b : U1_b;
    int tid = threadIdx.x;

    float x = v[tid];
    float ss = x * x;
    #pragma unroll
    for (int off = 16; off >= 1; off >>= 1) ss += __shfl_xor_sync(0xffffffff, ss, off);
    __shared__ float warp_ss[8];
    __shared__ float scale_sh;
    if ((tid & 31) == 0) warp_ss[tid >> 5] = ss;
    __syncthreads();
    if (tid == 0) {
        float tot = 0.f;
        #pragma unroll
        for (int w = 0; w < 8; w++) tot += warp_ss[w];
        scale_sh = g[l] * rsqrtf(tot);
    }
    __syncthreads();
    g_W[row * 256 + tid] = x * scale_sh;
    if (tid == 0) g_bias[row] = bb[l];

    int idx = blockIdx.x * 256 + tid;
    if (idx < B * LR) g_s[idx] = 0.f;
    if (idx < B * VD) g_vfinal[idx] = 0.f;
}

// ---------------------------------------------------------------------------
// Kernel C: fp16 tensor-core GEMM [65536x256] @ W^T[256x128] + fused epilogue.
// R3 structure (register prefetch, K-chunk 32), datatype fp16 m16n8k16.
// smem element = half2 (one k-pair). 36-word row stride -> conflict-free frags.
// grid 512 (row tiles of 128), block 256 (8 warps: 4 m x 2 n).
__global__ void __launch_bounds__(256, 2) k_main(const float* __restrict__ Vmat)
{
    __shared__ uint32_t As[128][36];   // [row][kpair] half2 bits; 16 used, pad 36
    __shared__ uint32_t Bs[128][36];   // [col][kpair]
    __shared__ float d_sh[128];
    __shared__ float s_sh[64];
    __shared__ float bias_sh[128];

    int tid = threadIdx.x;
    int lane = tid & 31, wid = tid >> 5;
    int warp_m = wid & 3, warp_n = wid >> 2;     // warp tile: 32 rows x 64 cols
    int qr = lane >> 2, qk = lane & 3;
    int tileRow0 = blockIdx.x * 128;
    int batch = blockIdx.x >> 4;                 // 16 tiles per batch

    if (tid < 128) { d_sh[tid] = 0.f; bias_sh[tid] = g_bias[tid]; }
    if (tid < 64) s_sh[tid] = 0.f;

    float acc[2][8][4];
    #pragma unroll
    for (int mt = 0; mt < 2; mt++)
        #pragma unroll
        for (int nt = 0; nt < 8; nt++)
            #pragma unroll
            for (int c = 0; c < 4; c++) acc[mt][nt][c] = 0.f;

    const float* Vbase = Vmat + (size_t)tileRow0 * VD;
    int lrow = tid >> 3;      // base row within the 32-row load slab
    int lkq  = tid & 7;       // float4 index within 32-k chunk

    float4 ra[4], rb[4];
    // prefetch chunk 0
    #pragma unroll
    for (int i = 0; i < 4; i++) {
        int r = i * 32 + lrow;
        ra[i] = *(const float4*)(Vbase + (size_t)r * VD + lkq * 4);
        rb[i] = *(const float4*)(g_W + r * 256 + lkq * 4);
    }

    for (int kc = 0; kc < 8; kc++) {
        __syncthreads();
        #pragma unroll
        for (int i = 0; i < 4; i++) {
            int r = i * 32 + lrow;
            As[r][lkq * 2]     = pack_h2(ra[i].x, ra[i].y);
            As[r][lkq * 2 + 1] = pack_h2(ra[i].z, ra[i].w);
            Bs[r][lkq * 2]     = pack_h2(rb[i].x, rb[i].y);
            Bs[r][lkq * 2 + 1] = pack_h2(rb[i].z, rb[i].w);
        }
        __syncthreads();
        if (kc < 7) {
            int k0 = (kc + 1) * 32;
            #pragma unroll
            for (int i = 0; i < 4; i++) {
                int r = i * 32 + lrow;
                ra[i] = *(const float4*)(Vbase + (size_t)r * VD + k0 + lkq * 4);
                rb[i] = *(const float4*)(g_W + r * 256 + k0 + lkq * 4);
            }
        }
        // chunk = 32 k = 16 kpairs = 2 mma k-steps (k16 each)
        #pragma unroll
        for (int ks = 0; ks < 2; ks++) {
            int kb = ks * 8 + qk;               // kpair index of low half
            uint32_t af[2][4];
            #pragma unroll
            for (int mt = 0; mt < 2; mt++) {
                int r = warp_m * 32 + mt * 16 + qr;
                af[mt][0] = As[r][kb];
                af[mt][1] = As[r + 8][kb];
                af[mt][2] = As[r][kb + 4];
                af[mt][3] = As[r + 8][kb + 4];
            }
            uint32_t bf[8][2];
            #pragma unroll
            for (int nt = 0; nt < 8; nt++) {
                int c = warp_n * 64 + nt * 8 + qr;
                bf[nt][0] = Bs[c][kb];
                bf[nt][1] = Bs[c][kb + 4];
            }
            #pragma unroll
            for (int mt = 0; mt < 2; mt++)
                #pragma unroll
                for (int nt = 0; nt < 8; nt++)
                    mma_f16(acc[mt][nt], af[mt], bf[nt]);
        }
    }

    // ---- epilogue: bias+relu, d per row, dr, store right, accumulate s ----
    float be[8], bo[8];
    #pragma unroll
    for (int nt = 0; nt < 8; nt++) {
        int c0 = warp_n * 64 + nt * 8 + qk * 2;
        be[nt] = bias_sh[c0];
        bo[nt] = bias_sh[c0 + 1];
    }

    #pragma unroll
    for (int mt = 0; mt < 2; mt++) {
        #pragma unroll
        for (int h = 0; h < 2; h++) {
            float dpart = 0.f;
            #pragma unroll
            for (int nt = 0; nt < 8; nt++) {
                float rv = fmaxf(acc[mt][nt][h * 2]     + be[nt], 0.f);
                float lv = fmaxf(acc[mt][nt][h * 2 + 1] + bo[nt], 0.f);
                acc[mt][nt][h * 2] = rv;
                acc[mt][nt][h * 2 + 1] = lv;
                dpart = fmaf(rv, lv, dpart);
            }
            dpart += __shfl_xor_sync(0xffffffff, dpart, 1);
            dpart += __shfl_xor_sync(0xffffffff, dpart, 2);
            if (qk == 0) {
                int rl = warp_m * 32 + mt * 16 + h * 8 + qr;
                atomicAdd(&d_sh[rl], dpart);
            }
        }
    }
    __syncthreads();

    float s_t[8];
    #pragma unroll
    for (int nt = 0; nt < 8; nt++) s_t[nt] = 0.f;

    #pragma unroll
    for (int mt = 0; mt < 2; mt++) {
        #pragma unroll
        for (int h = 0; h < 2; h++) {
            int rl = warp_m * 32 + mt * 16 + h * 8 + qr;
            float dr = rsqrtf(d_sh[rl] + EPS_DIAG);
            int row = tileRow0 + rl;
            if (warp_n == 0 && qk == 0) g_dr[row] = dr;
            float* rp = g_right + (size_t)row * LR + warp_n * 32;
            #pragma unroll
            for (int nt = 0; nt < 8; nt++) {
                rp[nt * 4 + qk] = acc[mt][nt][h * 2];
                s_t[nt] = fmaf(dr, acc[mt][nt][h * 2 + 1], s_t[nt]);
            }
        }
    }
    #pragma unroll
    for (int off = 4; off <= 16; off <<= 1)
        #pragma unroll
        for (int nt = 0; nt < 8; nt++)
            s_t[nt] += __shfl_xor_sync(0xffffffff, s_t[nt], off);
    if (qr == 0) {
        #pragma unroll
        for (int nt = 0; nt < 8; nt++)
            atomicAdd(&s_sh[warp_n * 32 + nt * 4 + qk], s_t[nt]);
    }
    __syncthreads();
    if (tid < 64) atomicAdd(&g_s[batch * LR + tid], s_sh[tid]);
}

// ---------------------------------------------------------------------------
// Kernel D (R3 version): c[m] = N+1 - dr[m]*(s . right[m]); v_final += ...
__global__ void __launch_bounds__(256) k_final(const float* __restrict__ Vmat)
{
    __shared__ float s_sh[64];
    __shared__ float c_sh[256];
    int tid = threadIdx.x;
    int b = blockIdx.y;
    int m0 = blockIdx.x * 256;

    if (tid < 64) s_sh[tid] = g_s[b * LR + tid];
    __syncthreads();

    int row = b * N + m0 + tid;
    const float4* rp = (const float4*)(g_right + (size_t)row * LR);
    float dot = 0.f;
    #pragma unroll
    for (int q = 0; q < 16; q++) {
        float4 v = rp[q];
        dot = fmaf(v.x, s_sh[q * 4 + 0], dot);
        dot = fmaf(v.y, s_sh[q * 4 + 1], dot);
        dot = fmaf(v.z, s_sh[q * 4 + 2], dot);
        dot = fmaf(v.w, s_sh[q * 4 + 3], dot);
    }
    c_sh[tid] = (float)(N + 1) - g_dr[row] * dot;
    __syncthreads();

    const float* Vp = Vmat + ((size_t)b * N + m0) * VD + tid;
    float vacc = 0.f;
    #pragma unroll 8
    for (int m = 0; m < 256; m++) vacc = fmaf(c_sh[m], Vp[(size_t)m * VD], vacc);
    atomicAdd(&g_vfinal[b * VD + tid], vacc * (1.0f / (float)N));
}

// ---------------------------------------------------------------------------
// Kernel E (R3 version): feat + BatchNorm. grid 128, block 512 (2 cols/block)
__global__ void __launch_bounds__(512) k_bn(const float* __restrict__ W_lin,
                                            const float* __restrict__ b_lin,
                                            const float* __restrict__ gamma,
                                            const float* __restrict__ beta,
                                            float* __restrict__ out)
{
    int tid = threadIdx.x;
    int w = tid >> 5, lane = tid & 31;
    int e_loc = w >> 3;                      // 0..1
    int e = blockIdx.x * 2 + e_loc;
    int bat = (w & 7) * 4 + (lane >> 3);     // 0..31
    int dl = lane & 7;

    const float* wrow = W_lin + e * VD;
    const float* vrow = g_vfinal + bat * VD;
    float part = 0.f;
    #pragma unroll
    for (int j = 0; j < 32; j++) {
        int d = dl + 8 * j;
        part = fmaf(vrow[d], wrow[d], part);
    }
    part += __shfl_xor_sync(0xffffffff, part, 1);
    part += __shfl_xor_sync(0xffffffff, part, 2);
    part += __shfl_xor_sync(0xffffffff, part, 4);

    __shared__ float feats[2][32];
    if (dl == 0) feats[e_loc][bat] = part + b_lin[e];
    __syncthreads();

    if (tid < 64) {
        int el = tid >> 5;
        int bb = tid & 31;
        float f = feats[el][bb];
        float mu = f;
        #pragma unroll
        for (int off = 16; off >= 1; off >>= 1) mu += __shfl_xor_sync(0xffffffff, mu, off);
        mu *= (1.0f / 32.0f);
        float df = f - mu;
        float vv = df * df;
        #pragma unroll
        for (int off = 16; off >= 1; off >>= 1) vv += __shfl_xor_sync(0xffffffff, vv, off);
        vv *= (1.0f / 32.0f);
        int eo = blockIdx.x * 2 + el;
        out[bb * EMB + eo] = df * rsqrtf(vv + EPS_BN) * gamma[eo] + beta[eo];
    }
}

// ---------------------------------------------------------------------------
extern "C" void kernel_launch(void* const* d_in, const int* in_sizes, int n_in,
                              void* d_out, int out_size)
{
    const float* Vmat  = (const float*)d_in[0];
    const float* U1_v  = (const float*)d_in[1];
    const float* U1_g  = (const float*)d_in[2];
    const float* U1_b  = (const float*)d_in[3];
    const float* U2_v  = (const float*)d_in[4];
    const float* U2_g  = (const float*)d_in[5];
    const float* U2_b  = (const float*)d_in[6];
    const float* W_lin = (const float*)d_in[7];
    const float* b_lin = (const float*)d_in[8];
    const float* gamma = (const float*)d_in[9];
    const float* beta  = (const float*)d_in[10];
    float* out = (float*)d_out;

    k_weightnorm<<<128, 256>>>(U1_v, U1_g, U1_b, U2_v, U2_g, U2_b);
    k_main<<<ROWS / 128, 256>>>(Vmat);
    k_final<<<dim3(8, B), 256>>>(Vmat);
    k_bn<<<EMB / 2, 512>>>(W_lin, b_lin, gamma, beta, out);
}

// round 7
// speedup vs baseline: 1.3669x; 1.0323x over previous
#include <cuda_runtime.h>
#include <cuda_fp16.h>
#include <cuda_bf16.h>
#include <cstdint>

#define B   32
#define N   2048
#define VD  256
#define LR  64
#define EMB 256
#define ROWS (B*N)
#define EPS_DIAG 1e-6f
#define EPS_BN   1e-5f

// Scratch (device globals)
__device__ float g_W[128 * 256];      // interleaved: row c even -> W1[c/2], odd -> W2[c/2]
__device__ float g_bias[128];
__device__ float g_right[(size_t)ROWS * LR];   // 16 MB
__device__ float g_dr[ROWS];
__device__ float g_s[B * LR];
__device__ float g_vfinal[B * VD];

__device__ __forceinline__ uint32_t pack_h2(float lo, float hi) {
    __half2 h = __floats2half2_rn(lo, hi);
    return *(uint32_t*)&h;
}

__device__ __forceinline__ void mma_f16(float c[4], const uint32_t a[4], const uint32_t b[2]) {
    asm volatile(
        "mma.sync.aligned.m16n8k16.row.col.f32.f16.f16.f32 "
        "{%0,%1,%2,%3}, {%4,%5,%6,%7}, {%8,%9}, {%0,%1,%2,%3};"
        : "+f"(c[0]), "+f"(c[1]), "+f"(c[2]), "+f"(c[3])
        : "r"(a[0]), "r"(a[1]), "r"(a[2]), "r"(a[3]), "r"(b[0]), "r"(b[1]));
}

__device__ __forceinline__ void ldsm_x4(uint32_t r[4], uint32_t addr) {
    asm volatile("ldmatrix.sync.aligned.m8n8.x4.shared.b16 {%0,%1,%2,%3}, [%4];"
        : "=r"(r[0]), "=r"(r[1]), "=r"(r[2]), "=r"(r[3]) : "r"(addr));
}

// ---------------------------------------------------------------------------
// Kernel A: weight norm + zero accumulators.  grid 128, block 256
__global__ void k_weightnorm(const float* __restrict__ U1_v, const float* __restrict__ U1_g,
                             const float* __restrict__ U1_b, const float* __restrict__ U2_v,
                             const float* __restrict__ U2_g, const float* __restrict__ U2_b)
{
    int row = blockIdx.x;
    int l = row >> 1;
    bool odd = row & 1;
    const float* v = (odd ? U2_v : U1_v) + l * VD;
    const float* g = odd ? U2_g : U1_g;
    const float* bb = odd ? U2_b : U1_b;
    int tid = threadIdx.x;

    float x = v[tid];
    float ss = x * x;
    #pragma unroll
    for (int off = 16; off >= 1; off >>= 1) ss += __shfl_xor_sync(0xffffffff, ss, off);
    __shared__ float warp_ss[8];
    __shared__ float scale_sh;
    if ((tid & 31) == 0) warp_ss[tid >> 5] = ss;
    __syncthreads();
    if (tid == 0) {
        float tot = 0.f;
        #pragma unroll
        for (int w = 0; w < 8; w++) tot += warp_ss[w];
        scale_sh = g[l] * rsqrtf(tot);
    }
    __syncthreads();
    g_W[row * 256 + tid] = x * scale_sh;
    if (tid == 0) g_bias[row] = bb[l];

    int idx = blockIdx.x * 256 + tid;
    if (idx < B * LR) g_s[idx] = 0.f;
    if (idx < B * VD) g_vfinal[idx] = 0.f;
}

// ---------------------------------------------------------------------------
// Kernel C: fp16 tensor-core GEMM [65536x256] @ W^T[256x128] + fused epilogue.
// LDSM fragment loads (6 ldmatrix.x4 per k16-step), K-chunk 32, reg prefetch.
// grid 512 (row tiles of 128), block 256 (8 warps: 4 m x 2 n).
__global__ void __launch_bounds__(256, 2) k_main(const float* __restrict__ Vmat)
{
    __shared__ uint32_t As[128][36];   // [row][kpair] half2 bits; 16 used, pad 36
    __shared__ uint32_t Bs[128][36];   // [col][kpair]
    __shared__ float d_sh[128];
    __shared__ float s_sh[64];
    __shared__ float bias_sh[128];

    int tid = threadIdx.x;
    int lane = tid & 31, wid = tid >> 5;
    int warp_m = wid & 3, warp_n = wid >> 2;     // warp tile: 32 rows x 64 cols
    int qr = lane >> 2, qk = lane & 3;
    int tileRow0 = blockIdx.x * 128;
    int batch = blockIdx.x >> 4;                 // 16 tiles per batch

    if (tid < 128) { d_sh[tid] = 0.f; bias_sh[tid] = g_bias[tid]; }
    if (tid < 64) s_sh[tid] = 0.f;

    float acc[2][8][4];
    #pragma unroll
    for (int mt = 0; mt < 2; mt++)
        #pragma unroll
        for (int nt = 0; nt < 8; nt++)
            #pragma unroll
            for (int c = 0; c < 4; c++) acc[mt][nt][c] = 0.f;

    const float* Vbase = Vmat + (size_t)tileRow0 * VD;
    int lrow = tid >> 3;      // base row within the 32-row load slab
    int lkq  = tid & 7;       // float4 index within 32-k chunk

    // Per-lane ldmatrix base addresses (ks=0); ks=1 adds 32 bytes (8 kpairs).
    uint32_t sA = (uint32_t)__cvta_generic_to_shared(&As[0][0]);
    uint32_t sB = (uint32_t)__cvta_generic_to_shared(&Bs[0][0]);
    int l8 = lane & 7, lm = lane >> 3;   // lm = matrix index 0..3
    uint32_t a_base[2], b_base[4];
    #pragma unroll
    for (int mt = 0; mt < 2; mt++) {
        // matrices: m0=(rows 0-7, k-lo) m1=(rows 8-15, k-lo) m2=(rows 0-7, k-hi) m3=(rows 8-15, k-hi)
        int row = warp_m * 32 + mt * 16 + (lm & 1) * 8 + l8;
        int kp  = (lm >> 1) * 4;
        a_base[mt] = sA + (uint32_t)(row * 36 + kp) * 4;
    }
    #pragma unroll
    for (int j = 0; j < 4; j++) {
        // matrices: m0=(nt=2j, k-lo) m1=(nt=2j, k-hi) m2=(nt=2j+1, k-lo) m3=(nt=2j+1, k-hi)
        int c  = warp_n * 64 + (2 * j + (lm >> 1)) * 8 + l8;
        int kp = (lm & 1) * 4;
        b_base[j] = sB + (uint32_t)(c * 36 + kp) * 4;
    }

    float4 ra[4], rb[4];
    // prefetch chunk 0
    #pragma unroll
    for (int i = 0; i < 4; i++) {
        int r = i * 32 + lrow;
        ra[i] = *(const float4*)(Vbase + (size_t)r * VD + lkq * 4);
        rb[i] = *(const float4*)(g_W + r * 256 + lkq * 4);
    }

    for (int kc = 0; kc < 8; kc++) {
        __syncthreads();
        #pragma unroll
        for (int i = 0; i < 4; i++) {
            int r = i * 32 + lrow;
            As[r][lkq * 2]     = pack_h2(ra[i].x, ra[i].y);
            As[r][lkq * 2 + 1] = pack_h2(ra[i].z, ra[i].w);
            Bs[r][lkq * 2]     = pack_h2(rb[i].x, rb[i].y);
            Bs[r][lkq * 2 + 1] = pack_h2(rb[i].z, rb[i].w);
        }
        __syncthreads();
        if (kc < 7) {
            int k0 = (kc + 1) * 32;
            #pragma unroll
            for (int i = 0; i < 4; i++) {
                int r = i * 32 + lrow;
                ra[i] = *(const float4*)(Vbase + (size_t)r * VD + k0 + lkq * 4);
                rb[i] = *(const float4*)(g_W + r * 256 + k0 + lkq * 4);
            }
        }
        // chunk = 32 k = 2 mma k16-steps
        #pragma unroll
        for (int ks = 0; ks < 2; ks++) {
            uint32_t koff = ks * 32;             // 8 kpairs * 4B
            uint32_t af[2][4];
            ldsm_x4(af[0], a_base[0] + koff);
            ldsm_x4(af[1], a_base[1] + koff);
            uint32_t bf[8][2];
            #pragma unroll
            for (int j = 0; j < 4; j++) {
                uint32_t t[4];
                ldsm_x4(t, b_base[j] + koff);
                bf[2 * j][0]     = t[0];
                bf[2 * j][1]     = t[1];
                bf[2 * j + 1][0] = t[2];
                bf[2 * j + 1][1] = t[3];
            }
            #pragma unroll
            for (int mt = 0; mt < 2; mt++)
                #pragma unroll
                for (int nt = 0; nt < 8; nt++)
                    mma_f16(acc[mt][nt], af[mt], bf[nt]);
        }
    }

    // ---- epilogue: bias+relu, d per row, dr, store right, accumulate s ----
    float be[8], bo[8];
    #pragma unroll
    for (int nt = 0; nt < 8; nt++) {
        int c0 = warp_n * 64 + nt * 8 + qk * 2;
        be[nt] = bias_sh[c0];
        bo[nt] = bias_sh[c0 + 1];
    }

    #pragma unroll
    for (int mt = 0; mt < 2; mt++) {
        #pragma unroll
        for (int h = 0; h < 2; h++) {
            float dpart = 0.f;
            #pragma unroll
            for (int nt = 0; nt < 8; nt++) {
                float rv = fmaxf(acc[mt][nt][h * 2]     + be[nt], 0.f);
                float lv = fmaxf(acc[mt][nt][h * 2 + 1] + bo[nt], 0.f);
                acc[mt][nt][h * 2] = rv;
                acc[mt][nt][h * 2 + 1] = lv;
                dpart = fmaf(rv, lv, dpart);
            }
            dpart += __shfl_xor_sync(0xffffffff, dpart, 1);
            dpart += __shfl_xor_sync(0xffffffff, dpart, 2);
            if (qk == 0) {
                int rl = warp_m * 32 + mt * 16 + h * 8 + qr;
                atomicAdd(&d_sh[rl], dpart);
            }
        }
    }
    __syncthreads();

    float s_t[8];
    #pragma unroll
    for (int nt = 0; nt < 8; nt++) s_t[nt] = 0.f;

    #pragma unroll
    for (int mt = 0; mt < 2; mt++) {
        #pragma unroll
        for (int h = 0; h < 2; h++) {
            int rl = warp_m * 32 + mt * 16 + h * 8 + qr;
            float dr = rsqrtf(d_sh[rl] + EPS_DIAG);
            int row = tileRow0 + rl;
            if (warp_n == 0 && qk == 0) g_dr[row] = dr;
            float* rp = g_right + (size_t)row * LR + warp_n * 32;
            #pragma unroll
            for (int nt = 0; nt < 8; nt++) {
                rp[nt * 4 + qk] = acc[mt][nt][h * 2];
                s_t[nt] = fmaf(dr, acc[mt][nt][h * 2 + 1], s_t[nt]);
            }
        }
    }
    #pragma unroll
    for (int off = 4; off <= 16; off <<= 1)
        #pragma unroll
        for (int nt = 0; nt < 8; nt++)
            s_t[nt] += __shfl_xor_sync(0xffffffff, s_t[nt], off);
    if (qr == 0) {
        #pragma unroll
        for (int nt = 0; nt < 8; nt++)
            atomicAdd(&s_sh[warp_n * 32 + nt * 4 + qk], s_t[nt]);
    }
    __syncthreads();
    if (tid < 64) atomicAdd(&g_s[batch * LR + tid], s_sh[tid]);
}

// ---------------------------------------------------------------------------
// Kernel D (R3 version): c[m] = N+1 - dr[m]*(s . right[m]); v_final += ...
__global__ void __launch_bounds__(256) k_final(const float* __restrict__ Vmat)
{
    __shared__ float s_sh[64];
    __shared__ float c_sh[256];
    int tid = threadIdx.x;
    int b = blockIdx.y;
    int m0 = blockIdx.x * 256;

    if (tid < 64) s_sh[tid] = g_s[b * LR + tid];
    __syncthreads();

    int row = b * N + m0 + tid;
    const float4* rp = (const float4*)(g_right + (size_t)row * LR);
    float dot = 0.f;
    #pragma unroll
    for (int q = 0; q < 16; q++) {
        float4 v = rp[q];
        dot = fmaf(v.x, s_sh[q * 4 + 0], dot);
        dot = fmaf(v.y, s_sh[q * 4 + 1], dot);
        dot = fmaf(v.z, s_sh[q * 4 + 2], dot);
        dot = fmaf(v.w, s_sh[q * 4 + 3], dot);
    }
    c_sh[tid] = (float)(N + 1) - g_dr[row] * dot;
    __syncthreads();

    const float* Vp = Vmat + ((size_t)b * N + m0) * VD + tid;
    float vacc = 0.f;
    #pragma unroll 8
    for (int m = 0; m < 256; m++) vacc = fmaf(c_sh[m], Vp[(size_t)m * VD], vacc);
    atomicAdd(&g_vfinal[b * VD + tid], vacc * (1.0f / (float)N));
}

// ---------------------------------------------------------------------------
// Kernel E: feat = v_final @ W_lin^T + b_lin; BatchNorm over B (biased var).
// grid 256 (one e per block), block 128. wrow cached in smem, float4 loads.
__global__ void __launch_bounds__(128) k_bn(const float* __restrict__ W_lin,
                                            const float* __restrict__ b_lin,
                                            const float* __restrict__ gamma,
                                            const float* __restrict__ beta,
                                            float* __restrict__ out)
{
    int e = blockIdx.x;
    int tid = threadIdx.x;
    __shared__ float4 w_sh[64];      // 256 floats
    __shared__ float feats[32];

    if (tid < 64) w_sh[tid] = ((const float4*)(W_lin + e * VD))[tid];
    __syncthreads();

    int bat = tid >> 2;              // 0..31
    int q0  = tid & 3;               // float4 phase
    const float4* vr = (const float4*)(g_vfinal + bat * VD);
    float dot = 0.f;
    #pragma unroll
    for (int q = 0; q < 16; q++) {
        float4 v = vr[q * 4 + q0];
        float4 w = w_sh[q * 4 + q0];
        dot = fmaf(v.x, w.x, dot);
        dot = fmaf(v.y, w.y, dot);
        dot = fmaf(v.z, w.z, dot);
        dot = fmaf(v.w, w.w, dot);
    }
    dot += __shfl_xor_sync(0xffffffff, dot, 1);
    dot += __shfl_xor_sync(0xffffffff, dot, 2);
    if (q0 == 0) feats[bat] = dot + b_lin[e];
    __syncthreads();

    if (tid < 32) {
        float f = feats[tid];
        float mu = f;
        #pragma unroll
        for (int off = 16; off >= 1; off >>= 1) mu += __shfl_xor_sync(0xffffffff, mu, off);
        mu *= (1.0f / 32.0f);
        float df = f - mu;
        float vv = df * df;
        #pragma unroll
        for (int off = 16; off >= 1; off >>= 1) vv += __shfl_xor_sync(0xffffffff, vv, off);
        vv *= (1.0f / 32.0f);
        out[tid * EMB + e] = df * rsqrtf(vv + EPS_BN) * gamma[e] + beta[e];
    }
}

// ---------------------------------------------------------------------------
extern "C" void kernel_launch(void* const* d_in, const int* in_sizes, int n_in,
                              void* d_out, int out_size)
{
    const float* Vmat  = (const float*)d_in[0];
    const float* U1_v  = (const float*)d_in[1];
    const float* U1_g  = (const float*)d_in[2];
    const float* U1_b  = (const float*)d_in[3];
    const float* U2_v  = (const float*)d_in[4];
    const float* U2_g  = (const float*)d_in[5];
    const float* U2_b  = (const float*)d_in[6];
    const float* W_lin = (const float*)d_in[7];
    const float* b_lin = (const float*)d_in[8];
    const float* gamma = (const float*)d_in[9];
    const float* beta  = (const float*)d_in[10];
    float* out = (float*)d_out;

    k_weightnorm<<<128, 256>>>(U1_v, U1_g, U1_b, U2_v, U2_g, U2_b);
    k_main<<<ROWS / 128, 256>>>(Vmat);
    k_final<<<dim3(8, B), 256>>>(Vmat);
    k_bn<<<EMB, 128>>>(W_lin, b_lin, gamma, beta, out);
}